// round 17
// baseline (speedup 1.0000x reference)
#include <cuda_runtime.h>
#include <cuda_fp16.h>
#include <cstdint>

// ============================================================================
// drug[32768,4,512] f32, Wk/Wq/Wv[512,64] f32 -> out[32768,64] f32
// out[b] = max_n softmax_m( (X Wk)(X Wq)^T )[n,:] @ (X Wv),  X = drug[b] (4x512)
//
// R17: 192 threads/CTA (6 warps, wr2 x wc3, warp tile 32x64), 2 CTAs/SM ->
// 170-reg cap. Whole-slice B (16 uint4) preloaded into REGISTERS so LDG
// latency amortizes over 48 MMAs; ptxas gets slack to pipeline A-LDS.
// Otherwise R15: fp16 m16n8k16, cp.async A->ST->convert (folded into kt loop),
// B pre-permuted fragment-order in gmem, 1 __syncthreads per slice.
// ============================================================================

namespace {
constexpr int F        = 512;
constexpr int KT       = 64;
constexpr int NSLICES  = F / KT;      // 8
constexpr int MROWS    = 64;          // 16 batches per CTA
constexpr int THREADS  = 192;         // 6 warps: wr(2) x wc(3)
constexpr int PITCHC   = 200;

constexpr int PST      = 68;
constexpr int ST_BYTES = MROWS * PST * 4;          // 17408 (x2)
constexpr int AP_BYTES = 16 * 32 * 16;             // 8192 (x2)
constexpr int OFF_ST   = 0;
constexpr int OFF_AP   = 2 * ST_BYTES;             // 34816
constexpr int PIPE_BYTES = OFF_AP + 2 * AP_BYTES;  // 51200
constexpr int C_BYTES  = MROWS * PITCHC * 4;       // 51200 (aliases pipeline)
constexpr int SMEM_BYTES = (PIPE_BYTES > C_BYTES) ? PIPE_BYTES : C_BYTES;
}

__device__ __forceinline__ uint32_t smem_u32(const void* p) {
    uint32_t a;
    asm("{ .reg .u64 t; cvta.to.shared.u64 t, %1; cvt.u32.u64 %0, t; }"
        : "=r"(a) : "l"(p));
    return a;
}
__device__ __forceinline__ uint32_t pack_h2(float lo, float hi) {
    __half l = __float2half_rn(lo), h = __float2half_rn(hi);
    return (uint32_t)__half_as_ushort(l) | ((uint32_t)__half_as_ushort(h) << 16);
}
__device__ __forceinline__ void mma_f16(float* c, const uint32_t* a,
                                        uint32_t b0, uint32_t b1) {
    asm("mma.sync.aligned.m16n8k16.row.col.f32.f16.f16.f32 "
        "{%0,%1,%2,%3}, {%4,%5,%6,%7}, {%8,%9}, {%0,%1,%2,%3};"
        : "+f"(c[0]), "+f"(c[1]), "+f"(c[2]), "+f"(c[3])
        : "r"(a[0]), "r"(a[1]), "r"(a[2]), "r"(a[3]), "r"(b0), "r"(b1));
}
__device__ __forceinline__ void cp16(uint32_t smem_dst, const void* gmem_src) {
    asm volatile("cp.async.cg.shared.global [%0], [%1], 16;"
                 :: "r"(smem_dst), "l"(gmem_src) : "memory");
}
__device__ __forceinline__ void cp_commit() {
    asm volatile("cp.async.commit_group;" ::: "memory");
}
template <int N>
__device__ __forceinline__ void cp_wait() {
    asm volatile("cp.async.wait_group %0;" :: "n"(N) : "memory");
}

// ---- B: fp16, fragment order for wc(3) x 8-n8 warp tiles (one-time) --------
// per slice: [wc=3][kt=4][j=4][lane=32][pos=4] uint32 (2 fp16) = 6144 u32 = 24KB
__device__ __align__(16) uint32_t g_BP[NSLICES][6144];

__global__ void conv_w_kernel(const float* __restrict__ Wk,
                              const float* __restrict__ Wq,
                              const float* __restrict__ Wv) {
    int idx  = blockIdx.x * 256 + threadIdx.x;   // 0..49151
    int pos  = idx & 3;
    int lane = (idx >> 2) & 31;
    int j    = (idx >> 7) & 3;
    int kt   = (idx >> 9) & 3;
    int rest = idx >> 11;          // 0..23 = s*3 + wc
    int wc   = rest % 3;
    int s    = rest / 3;

    int f  = j * 4 + pos;          // 0..15
    int ng = f >> 1;               // 0..7
    int h  = f & 1;
    int n  = wc * 64 + ng * 8 + (lane >> 2);
    int k  = s * KT + kt * 16 + (lane & 3) * 2 + h * 8;

    const float* W = (n < 64) ? Wk : ((n < 128) ? Wq : Wv);
    int col = n % 64;
    float lo = W[k * 64 + col];
    float hi = W[(k + 1) * 64 + col];
    g_BP[s][(((wc * 4 + kt) * 4 + j) * 32 + lane) * 4 + pos] = pack_h2(lo, hi);
}

// ---------------- main fused kernel ----------------
__global__ __launch_bounds__(THREADS, 2)
void attn_mma_kernel(const float* __restrict__ drug, float* __restrict__ out) {
    extern __shared__ __align__(128) char sm[];
    const uint32_t sb = smem_u32(sm);
    const int tid  = threadIdx.x;
    const int wid  = tid >> 5;
    const int lane = tid & 31;
    const int wr   = wid & 1;          // 2 row groups (32 rows)
    const int wc   = wid >> 1;         // 3 col groups (64 cols)
    const int R0   = wr * 32;
    const int C0   = wc * 64;
    const int row0 = blockIdx.x * MROWS;

    auto issue_A = [&](int s, int par) {
        uint32_t dst = sb + OFF_ST + par * ST_BYTES;
        const float* src = drug + (size_t)row0 * F + s * KT;
        #pragma unroll
        for (int i = 0; i < 6; i++) {
            int idx = tid + i * THREADS;      // 16B chunks, 1024 total
            if (idx < 1024) {
                int r   = idx >> 4;
                int c16 = idx & 15;
                cp16(dst + (uint32_t)(r * PST * 4 + c16 * 16),
                     src + (size_t)r * F + c16 * 4);
            }
        }
    };
    // one chunk (item = tid + i*192, item<512) of ST[par] -> AP[abuf]
    auto convert_chunk = [&](int par, int abuf, int i) {
        int item = tid + i * THREADS;
        if (item < 512) {
            const float* stf =
                reinterpret_cast<const float*>(sm + OFF_ST + par * ST_BYTES);
            char* apb = sm + OFF_AP + abuf * AP_BYTES;
            int fg  = item >> 5;
            int ln  = item & 31;
            int ktq = fg >> 2;
            int wrq = (fg >> 1) & 1;
            int rtq = fg & 1;
            int r1  = wrq * 32 + rtq * 16 + (ln >> 2);
            int c   = ktq * 16 + (ln & 3) * 2;
            const float* p0 = &stf[r1 * PST + c];
            const float* p1 = &stf[(r1 + 8) * PST + c];
            uint32_t a0 = pack_h2(p0[0], p0[1]);
            uint32_t a1 = pack_h2(p1[0], p1[1]);
            uint32_t a2 = pack_h2(p0[8], p0[9]);
            uint32_t a3 = pack_h2(p1[8], p1[9]);
            *reinterpret_cast<uint4*>(apb + (uint32_t)item * 16) =
                make_uint4(a0, a1, a2, a3);
        }
    };

    float acc[2][8][4];
    #pragma unroll
    for (int i = 0; i < 2; i++)
        #pragma unroll
        for (int j = 0; j < 8; j++)
            #pragma unroll
            for (int q = 0; q < 4; q++)
                acc[i][j][q] = 0.f;

    // ---- prologue ----
    issue_A(0, 0); cp_commit();      // GA(0)
    issue_A(1, 1); cp_commit();      // GA(1)
    cp_wait<1>();                    // GA(0) landed
    __syncthreads();
    convert_chunk(0, 0, 0);
    convert_chunk(0, 0, 1);
    convert_chunk(0, 0, 2);          // AP[0] <- slice 0

    // ---- main loop: ONE __syncthreads per slice ----
    for (int s = 0; s < NSLICES; s++) {
        const int buf  = s & 1;
        const int nbuf = buf ^ 1;

        cp_wait<0>();                // GA(s+1) landed (full slice of slack)
        __syncthreads();             // orders AP[buf] writes, GA(s+1) in ST,
                                     // and slice s-1's ST[buf] reads
        if (s + 2 < NSLICES) {
            issue_A(s + 2, buf);     // ST[buf] free now
            cp_commit();
        }

        // ---- preload whole slice of B into registers (16 LDG.128) ----
        const uint4* Bg = reinterpret_cast<const uint4*>(g_BP[s]);
        const uint32_t bbase = (uint32_t)wc * 512;
        uint4 bv[4][4];
        #pragma unroll
        for (int kt = 0; kt < 4; kt++)
            #pragma unroll
            for (int j = 0; j < 4; j++)
                bv[kt][j] = __ldg(&Bg[bbase + (uint32_t)((kt * 4 + j) * 32 + lane)]);

        const char* apb = sm + OFF_AP + buf * AP_BYTES;
        const bool cvt = (s + 1 < NSLICES);

        #pragma unroll
        for (int kt = 0; kt < 4; kt++) {
            uint32_t a[2][4];
            #pragma unroll
            for (int rt = 0; rt < 2; rt++) {
                int fg = kt * 4 + wr * 2 + rt;
                uint4 v = *reinterpret_cast<const uint4*>(
                    apb + (uint32_t)(fg * 32 + lane) * 16);
                a[rt][0] = v.x; a[rt][1] = v.y; a[rt][2] = v.z; a[rt][3] = v.w;
            }
            const uint32_t* b = reinterpret_cast<const uint32_t*>(bv[kt]);
            #pragma unroll
            for (int ng = 0; ng < 8; ng++)
                #pragma unroll
                for (int rt = 0; rt < 2; rt++)
                    mma_f16(acc[rt][ng], a[rt], b[2 * ng], b[2 * ng + 1]);

            // hide A(s+1) conversion under the MMA stream (AP[nbuf] idle)
            if (kt < 3 && cvt) convert_chunk(nbuf, nbuf, kt);
        }
        // no trailing sync: next slice's top barrier provides ordering
    }
    __syncthreads();     // all AP reads done before C park overwrites smem

    // ---- park C [64 x 192] fp32 in smem (aliases pipeline buffers) ----
    float* Cs = reinterpret_cast<float*>(sm);
    {
        int cr = lane >> 2;
        int cc = 2 * (lane & 3);
        #pragma unroll
        for (int rt = 0; rt < 2; rt++) {
            #pragma unroll
            for (int nt = 0; nt < 8; nt++) {
                int r = R0 + rt * 16 + cr;
                int c = C0 + nt * 8 + cc;
                *reinterpret_cast<float2*>(&Cs[r * PITCHC + c]) =
                    make_float2(acc[rt][nt][0], acc[rt][nt][1]);
                *reinterpret_cast<float2*>(&Cs[(r + 8) * PITCHC + c]) =
                    make_float2(acc[rt][nt][2], acc[rt][nt][3]);
            }
        }
    }
    __syncthreads();

    // ---- attention epilogue: 8 threads per batch (threads 0..127) ----
    if (tid < 128) {
        const int bl    = tid >> 3;        // 0..15
        const int g     = tid & 7;
        const int rbase = bl * 4;

        float kf[4][8], qf[4][8], vf[4][8];
        #pragma unroll
        for (int n = 0; n < 4; n++) {
            const float* p = &Cs[(rbase + n) * PITCHC + g * 8];
            *(float4*)&kf[n][0] = *(const float4*)(p);
            *(float4*)&kf[n][4] = *(const float4*)(p + 4);
            *(float4*)&qf[n][0] = *(const float4*)(p + 64);
            *(float4*)&qf[n][4] = *(const float4*)(p + 68);
            *(float4*)&vf[n][0] = *(const float4*)(p + 128);
            *(float4*)&vf[n][4] = *(const float4*)(p + 132);
        }

        float sc[4][4];
        #pragma unroll
        for (int n = 0; n < 4; n++)
            #pragma unroll
            for (int m = 0; m < 4; m++) {
                float a = 0.f;
                #pragma unroll
                for (int dd = 0; dd < 8; dd++)
                    a = fmaf(kf[n][dd], qf[m][dd], a);
                sc[n][m] = a;
            }
        #pragma unroll
        for (int off = 4; off > 0; off >>= 1)
            #pragma unroll
            for (int n = 0; n < 4; n++)
                #pragma unroll
                for (int m = 0; m < 4; m++)
                    sc[n][m] += __shfl_xor_sync(0xffffffffu, sc[n][m], off);

        float res[8];
        #pragma unroll
        for (int dd = 0; dd < 8; dd++) res[dd] = -3.402823466e38f;

        #pragma unroll
        for (int n = 0; n < 4; n++) {
            float mx = fmaxf(fmaxf(sc[n][0], sc[n][1]), fmaxf(sc[n][2], sc[n][3]));
            float p[4];
            float sum = 0.f;
            #pragma unroll
            for (int m = 0; m < 4; m++) { p[m] = expf(sc[n][m] - mx); sum += p[m]; }
            float inv = 1.f / sum;
            #pragma unroll
            for (int dd = 0; dd < 8; dd++) {
                float o = 0.f;
                #pragma unroll
                for (int m = 0; m < 4; m++)
                    o = fmaf(p[m] * inv, vf[m][dd], o);
                res[dd] = fmaxf(res[dd], o);
            }
        }

        const int b = blockIdx.x * 16 + bl;
        float* op = &out[(size_t)b * 64 + g * 8];
        *(float4*)op       = make_float4(res[0], res[1], res[2], res[3]);
        *(float4*)(op + 4) = make_float4(res[4], res[5], res[6], res[7]);
    }
}

// ---------------- launch ----------------
extern "C" void kernel_launch(void* const* d_in, const int* in_sizes, int n_in,
                              void* d_out, int out_size) {
    const float* drug = (const float*)d_in[0];
    const float* Wk   = (const float*)d_in[1];
    const float* Wq   = (const float*)d_in[2];
    const float* Wv   = (const float*)d_in[3];
    float* out        = (float*)d_out;

    conv_w_kernel<<<49152 / 256, 256>>>(Wk, Wq, Wv);

    cudaFuncSetAttribute(attn_mma_kernel,
                         cudaFuncAttributeMaxDynamicSharedMemorySize, SMEM_BYTES);
    attn_mma_kernel<<<2048, THREADS, SMEM_BYTES>>>(drug, out);
}